// round 7
// baseline (speedup 1.0000x reference)
#include <cuda_runtime.h>
#include <math.h>

// Problem constants
#define B_   512
#define T_   512
#define I_   128
#define H_   256
#define K_   (I_ + H_)          // 384 = x part (128) + h part (256)
#define RB   64                 // batch rows per block
#define CJ   16                 // h-columns per block
#define CC   64                 // gate columns per block (4 gates * CJ)
#define NBT  8                  // B_/RB
#define NGT  16                 // H_/CJ
#define NBLK (NBT*NGT)          // 128 persistent blocks (<= 148 SMs)
#define NTHR 256

#define SMEM_BYTES ((2*K_*CC + CC)*4 + RB*4)   // Wsm + Asm + bias + lengths = 197120 B

typedef unsigned long long ull;

// Persistent state (device globals; rewritten fully at t=0 each replay)
__device__ float g_h[B_*H_];
__device__ float g_c[B_*H_];
__device__ unsigned g_bar_count = 0;
__device__ unsigned g_bar_gen   = 0;

// ---- packed f32x2 helpers (exact fp32, 2x FFMA rate on sm_103a) ----
__device__ __forceinline__ void fma2(ull& d, ull a, ull b) {
    asm volatile("fma.rn.f32x2 %0, %1, %2, %0;" : "+l"(d) : "l"(a), "l"(b));
}
__device__ __forceinline__ ull pk2(float x, float y) {
    ull r;
    asm("mov.b64 %0, {%1, %2};" : "=l"(r)
        : "r"(__float_as_uint(x)), "r"(__float_as_uint(y)));
    return r;
}
__device__ __forceinline__ float2 unpk(ull v) {
    unsigned a, b;
    asm("mov.b64 {%0, %1}, %2;" : "=r"(a), "=r"(b) : "l"(v));
    return make_float2(__uint_as_float(a), __uint_as_float(b));
}

// ---- grid-wide sense barrier (128 co-resident blocks) ----
__device__ __forceinline__ void grid_sync(unsigned& gen) {
    __syncthreads();
    if (threadIdx.x == 0) {
        unsigned old;
        asm volatile("atom.add.acq_rel.gpu.u32 %0, [%1], %2;"
                     : "=r"(old) : "l"(&g_bar_count), "r"(1u) : "memory");
        if (old == NBLK - 1) {
            asm volatile("st.relaxed.gpu.u32 [%0], %1;"
                         :: "l"(&g_bar_count), "r"(0u) : "memory");
            asm volatile("red.add.release.gpu.u32 [%0], %1;"
                         :: "l"(&g_bar_gen), "r"(1u) : "memory");
        } else {
            unsigned target = gen + 1, cur;
            while (true) {
                asm volatile("ld.acquire.gpu.u32 %0, [%1];"
                             : "=r"(cur) : "l"(&g_bar_gen) : "memory");
                if ((int)(cur - target) >= 0) break;
                __nanosleep(32);
            }
        }
    }
    gen++;
    __syncthreads();
}

__device__ __forceinline__ float sigm(float x) { return 1.0f / (1.0f + expf(-x)); }

// ============================================================================
// Persistent LSTM kernel: 128 blocks loop over all T steps with a grid barrier
// between steps. Weight slice is SMEM-resident for the whole kernel.
// Block (bt, gt): batch rows [bt*64, +64), h-cols [gt*16, +16)
// (= gate columns {g*H + gt*16 + j : g<4, j<16}).
// ============================================================================
__global__ void __launch_bounds__(NTHR, 1)
lstm_persistent(const float* __restrict__ X,      // [B][T][I]
                const int*   __restrict__ lengths,
                const float* __restrict__ W_ih,   // [4H][I]
                const float* __restrict__ W_hh,   // [4H][H]
                const float* __restrict__ b_ih,
                const float* __restrict__ b_hh)
{
    extern __shared__ float sm[];
    float* Wsm = sm;                 // [K_][CC] k-major (c contiguous), 96 KB
    float* Asm = sm + K_*CC;         // [K_][RB] k-major (r contiguous), 96 KB
    float* Gsm = Asm;                // [RB][CC] gates tile, reuses Asm after GEMM
    float* bsm = sm + 2*K_*CC;       // [CC] combined bias
    int*   lsm = (int*)(bsm + CC);   // [RB] lengths

    const int tid  = threadIdx.x;
    const int bt   = blockIdx.x >> 4;
    const int gt   = blockIdx.x & 15;
    const int row0 = bt * RB;
    const int j0   = gt * CJ;

    unsigned gen = g_bar_gen;        // monotone across graph replays

    // ---- one-time: weight slice -> SMEM (k-major) ----
    for (int idx = tid; idx < CC * (K_/4); idx += NTHR) {
        int c  = idx & 63;
        int kq = idx >> 6;           // 0..95
        int k  = kq << 2;
        int g  = c >> 4, j = c & 15;
        int gi = g * H_ + j0 + j;    // global gate row, order [i,f,g,o]
        float4 w = (k < I_) ? *(const float4*)(W_ih + gi * I_ + k)
                            : *(const float4*)(W_hh + gi * H_ + (k - I_));
        Wsm[(k+0)*CC + c] = w.x;
        Wsm[(k+1)*CC + c] = w.y;
        Wsm[(k+2)*CC + c] = w.z;
        Wsm[(k+3)*CC + c] = w.w;
    }
    if (tid < CC) {
        int g = tid >> 4, j = tid & 15;
        int gi = g * H_ + j0 + j;
        bsm[tid] = b_ih[gi] + b_hh[gi];
    }
    if (tid < RB) lsm[tid] = lengths[row0 + tid];
    __syncthreads();

    // GEMM thread mapping: 16x16 thread grid, 4 rows x 4 cols micro-tile
    const int tc = tid & 15;         // cols tc*4 .. tc*4+3
    const int tr = tid >> 4;         // rows tr*4 .. tr*4+3
    ull biasd[4];
    #pragma unroll
    for (int c = 0; c < 4; ++c) {
        float bv = bsm[tc*4 + c];
        biasd[c] = pk2(bv, bv);      // same bias for the row pair
    }
    // update-phase mapping
    const int uj    = tid & 15;
    const int urb   = (tid >> 4) * 4;

    for (int t = 0; t < T_; ++t) {
        // ---- stage A = [x_t | h] into Asm[k][r] ----
        {
            const int r  = tid & 63;                  // fixed per thread
            const int q0 = tid >> 6;                  // 0..3
            const float* xrow = X + ((size_t)(row0 + r) * T_ + t) * I_;
            #pragma unroll
            for (int i = 0; i < 8; ++i) {             // x part: kq = q0 + 4i in [0,32)
                int k = (q0 + 4*i) << 2;
                float4 xv = *(const float4*)(xrow + k);
                Asm[(k+0)*RB + r] = xv.x;
                Asm[(k+1)*RB + r] = xv.y;
                Asm[(k+2)*RB + r] = xv.z;
                Asm[(k+3)*RB + r] = xv.w;
            }
            if (t > 0) {
                const float4* hrow = (const float4*)(g_h + (row0 + r) * H_);
                #pragma unroll
                for (int i = 0; i < 16; ++i) {        // h part: kq = q0 + 4i in [0,64)
                    int kq = q0 + 4*i;
                    float4 hv = __ldcg(hrow + kq);    // cross-SM producer -> L2 read
                    int k = I_ + (kq << 2);
                    Asm[(k+0)*RB + r] = hv.x;
                    Asm[(k+1)*RB + r] = hv.y;
                    Asm[(k+2)*RB + r] = hv.z;
                    Asm[(k+3)*RB + r] = hv.w;
                }
            }
        }
        __syncthreads();

        // ---- GEMM: gates(64x64) += A(64xK) * W^T, packed f32x2, row-paired ----
        ull acc[2][4];
        #pragma unroll
        for (int c = 0; c < 4; ++c) { acc[0][c] = biasd[c]; acc[1][c] = biasd[c]; }

        const int kend = (t == 0) ? I_ : K_;
        const float* Ap = Asm + tr * 4;
        const float* Wp = Wsm + tc * 4;
        #pragma unroll 4
        for (int k = 0; k < kend; ++k) {
            float4 a = *(const float4*)(Ap + k * RB);
            float4 w = *(const float4*)(Wp + k * CC);
            ull a01 = pk2(a.x, a.y);
            ull a23 = pk2(a.z, a.w);
            ull w0 = pk2(w.x, w.x), w1 = pk2(w.y, w.y);
            ull w2 = pk2(w.z, w.z), w3 = pk2(w.w, w.w);
            fma2(acc[0][0], a01, w0); fma2(acc[0][1], a01, w1);
            fma2(acc[0][2], a01, w2); fma2(acc[0][3], a01, w3);
            fma2(acc[1][0], a23, w0); fma2(acc[1][1], a23, w1);
            fma2(acc[1][2], a23, w2); fma2(acc[1][3], a23, w3);
        }
        __syncthreads();   // all Asm reads done before overwriting with gates

        // ---- spill gates tile to SMEM ----
        #pragma unroll
        for (int p = 0; p < 2; ++p) {
            #pragma unroll
            for (int c = 0; c < 4; ++c) {
                float2 v = unpk(acc[p][c]);
                Gsm[(tr*4 + p*2 + 0)*CC + tc*4 + c] = v.x;
                Gsm[(tr*4 + p*2 + 1)*CC + tc*4 + c] = v.y;
            }
        }
        __syncthreads();

        // ---- state update (4 cells per thread), packed-seq freeze mask ----
        #pragma unroll
        for (int rr = 0; rr < 4; ++rr) {
            int r  = urb + rr;
            float xi = Gsm[r*CC +      uj];
            float xf = Gsm[r*CC + 16 + uj];
            float xg = Gsm[r*CC + 32 + uj];
            float xo = Gsm[r*CC + 48 + uj];
            if (t < lsm[r]) {
                int gidx  = (row0 + r) * H_ + j0 + uj;
                float ig  = sigm(xi);
                float fg  = sigm(xf);
                float gg  = tanhf(xg);
                float og  = sigm(xo);
                float co  = (t == 0) ? 0.0f : g_c[gidx];   // thread-private across steps
                float cn  = fg * co + ig * gg;
                g_c[gidx] = cn;
                g_h[gidx] = og * tanhf(cn);
            }
        }

        grid_sync(gen);
    }
}

// ============================================================================
// LayerNorm over final hidden state: one warp per batch row
// ============================================================================
__global__ void ln_kernel(const float* __restrict__ gamma,
                          const float* __restrict__ beta,
                          float* __restrict__ out)
{
    int w    = (int)((blockIdx.x * blockDim.x + threadIdx.x) >> 5);
    int lane = threadIdx.x & 31;
    if (w >= B_) return;
    const float* hr = g_h + w * H_;
    float s = 0.0f, s2 = 0.0f;
    #pragma unroll
    for (int k = lane; k < H_; k += 32) { float v = hr[k]; s += v; s2 += v * v; }
    #pragma unroll
    for (int o = 16; o > 0; o >>= 1) {
        s  += __shfl_xor_sync(0xffffffffu, s,  o);
        s2 += __shfl_xor_sync(0xffffffffu, s2, o);
    }
    float mu  = s * (1.0f / H_);
    float var = fmaxf(s2 * (1.0f / H_) - mu * mu, 0.0f);
    float inv = rsqrtf(var + 1e-5f);
    #pragma unroll
    for (int k = lane; k < H_; k += 32) {
        out[w * H_ + k] = (hr[k] - mu) * inv * gamma[k] + beta[k];
    }
}

extern "C" void kernel_launch(void* const* d_in, const int* in_sizes, int n_in,
                              void* d_out, int out_size)
{
    const float* X      = (const float*)d_in[0];   // padded_X (B,T,I)
    const int*   lens   = (const int*)  d_in[1];   // lengths (B,)
    const float* W_ih   = (const float*)d_in[2];   // (4H, I)
    const float* W_hh   = (const float*)d_in[3];   // (4H, H)
    const float* b_ih   = (const float*)d_in[4];   // (4H,)
    const float* b_hh   = (const float*)d_in[5];   // (4H,)
    const float* gamma  = (const float*)d_in[6];   // (H,)
    const float* beta   = (const float*)d_in[7];   // (H,)
    float*       out    = (float*)d_out;           // (B, H)

    cudaFuncSetAttribute(lstm_persistent,
                         cudaFuncAttributeMaxDynamicSharedMemorySize, SMEM_BYTES);

    lstm_persistent<<<NBLK, NTHR, SMEM_BYTES>>>(X, lens, W_ih, W_hh, b_ih, b_hh);
    ln_kernel<<<(B_ * 32 + NTHR - 1) / NTHR, NTHR>>>(gamma, beta, out);
}

// round 8
// speedup vs baseline: 1.1775x; 1.1775x over previous
#include <cuda_runtime.h>
#include <math.h>

#define B_   512
#define T_   512
#define I_   128
#define H_   256
#define RB   64                 // batch rows per block
#define CC   64                 // gate cols per block (4 gates x 16 h-cols)
#define NBLK 128                // 8 batch tiles x 16 gate tiles (<=148 SMs)
#define NTHR 256
#define SROW 388                // padded row pitch in floats (97 chunks, odd -> no W bank conflicts)

#define SMEM_BYTES ((2*CC*SROW + CC)*4 + CC*4)   // Wsm + Asm + bias + lens = 199168 B

typedef unsigned long long ull;

// double-buffered hidden state (communication only; h,c live in registers)
__device__ float    g_h[2][B_*H_];
__device__ unsigned g_bar_count = 0;
__device__ unsigned g_bar_gen   = 0;

// packed f32x2 FMA: acc = (sum over even k, sum over odd k) — no operand duplication
__device__ __forceinline__ void fma2(ull& d, ull a, ull b) {
    asm("fma.rn.f32x2 %0, %1, %2, %0;" : "+l"(d) : "l"(a), "l"(b));
}
__device__ __forceinline__ float hsum(ull v) {
    unsigned a, b;
    asm("mov.b64 {%0, %1}, %2;" : "=r"(a), "=r"(b) : "l"(v));
    return __uint_as_float(a) + __uint_as_float(b);
}
__device__ __forceinline__ ull pklo(float x) {   // (x, 0)
    ull r;
    asm("mov.b64 %0, {%1, %2};" : "=l"(r) : "r"(__float_as_uint(x)), "r"(0u));
    return r;
}
__device__ __forceinline__ float sigm(float x) { return 1.0f / (1.0f + expf(-x)); }

// k-quad GEMM: acc[i][g] accumulates rows (tr*4+i) x gate-cols (16g+tc), k-paired
__device__ __forceinline__ void gemm_range(int q0, int q1,
                                           const float* __restrict__ pA,
                                           const float* __restrict__ pW,
                                           ull (&acc)[4][4])
{
    #pragma unroll 4
    for (int kq = q0; kq < q1; ++kq) {
        ulonglong2 a[4], w[4];
        #pragma unroll
        for (int i = 0; i < 4; ++i)
            a[i] = *(const ulonglong2*)(pA + i * SROW + kq * 4);
        #pragma unroll
        for (int g = 0; g < 4; ++g)
            w[g] = *(const ulonglong2*)(pW + g * 16 * SROW + kq * 4);
        #pragma unroll
        for (int i = 0; i < 4; ++i)
            #pragma unroll
            for (int g = 0; g < 4; ++g) {
                fma2(acc[i][g], a[i].x, w[g].x);
                fma2(acc[i][g], a[i].y, w[g].y);
            }
    }
}

__global__ void __launch_bounds__(NTHR, 1)
lstm_persistent(const float* __restrict__ X,      // [B][T][I]
                const int*   __restrict__ lengths,
                const float* __restrict__ W_ih,   // [4H][I]
                const float* __restrict__ W_hh,   // [4H][H]
                const float* __restrict__ b_ih,
                const float* __restrict__ b_hh)
{
    extern __shared__ float sm[];
    float* Wsm = sm;                  // [CC][SROW]  (gate-row major, k contiguous)
    float* Asm = sm + CC * SROW;      // [RB][SROW]  (row major: k 0..127 = x, 128..383 = h)
    float* bsm = sm + 2 * CC * SROW;  // [CC]
    int*   lsm = (int*)(bsm + CC);    // [RB]

    const int tid  = threadIdx.x;
    const int bt   = blockIdx.x >> 4;
    const int gt   = blockIdx.x & 15;
    const int row0 = bt * RB;
    const int j0   = gt * 16;

    unsigned gen0;
    asm volatile("ld.relaxed.gpu.u32 %0, [%1];" : "=r"(gen0) : "l"(&g_bar_gen) : "memory");

    // ---- one-time: W slice -> SMEM (native layout, just concatenated + padded) ----
    for (int idx = tid; idx < CC * 96; idx += NTHR) {
        int c  = idx / 96;
        int kq = idx - c * 96;
        int k  = kq * 4;
        int gi = (c >> 4) * H_ + j0 + (c & 15);   // gate order [i,f,g,o]
        float4 w = (k < I_) ? *(const float4*)(W_ih + gi * I_ + k)
                            : *(const float4*)(W_hh + gi * H_ + (k - I_));
        *(float4*)(Wsm + c * SROW + k) = w;
    }
    if (tid < CC) {
        int gi = (tid >> 4) * H_ + j0 + (tid & 15);
        bsm[tid] = b_ih[gi] + b_hh[gi];
    }
    if (tid < RB) lsm[tid] = lengths[row0 + tid];
    __syncthreads();

    // GEMM mapping: tc = h-col within tile (owns all 4 gates of it), tr = 4-row group
    const int tc = tid & 15;
    const int tr = tid >> 4;
    ull bias_d[4];
    #pragma unroll
    for (int g = 0; g < 4; ++g) bias_d[g] = pklo(bsm[g * 16 + tc]);

    const float* pA = Asm + tr * 4 * SROW;
    const float* pW = Wsm + tc * SROW;

    // staging mapping: thread (sr, sq) copies row sr, chunk stride 4
    const int sr = tid & 63;
    const int sq = tid >> 6;
    const float* xbase = X + (size_t)(row0 + sr) * T_ * I_;
    float* arow = Asm + sr * SROW;

    float c_reg[4] = {0.f, 0.f, 0.f, 0.f};
    float h_reg[4] = {0.f, 0.f, 0.f, 0.f};
    ull acc[4][4];

    // ---- prologue: stage x(0), x-part GEMM ----
    #pragma unroll
    for (int i2 = 0; i2 < 8; ++i2) {
        int ch = sq + 4 * i2;
        *(float4*)(arow + ch * 4) = __ldg((const float4*)(xbase + ch * 4));
    }
    __syncthreads();
    #pragma unroll
    for (int i = 0; i < 4; ++i)
        #pragma unroll
        for (int g = 0; g < 4; ++g) acc[i][g] = bias_d[g];
    gemm_range(0, 32, pA, pW, acc);

    for (int t = 0; t < T_; ++t) {
        if (t > 0) {
            // wait for step t-1 arrivals (h(t-1) globally visible)
            if (tid == 0) {
                unsigned target = gen0 + (unsigned)t, cur;
                while (true) {
                    asm volatile("ld.acquire.gpu.u32 %0, [%1];"
                                 : "=r"(cur) : "l"(&g_bar_gen) : "memory");
                    if ((int)(cur - target) >= 0) break;
                    __nanosleep(20);
                }
            }
            __syncthreads();
            // stage h(t-1) from the other buffer (L2; L1 not coherent cross-SM)
            const float* hb = g_h[(t - 1) & 1] + (row0 + sr) * H_;
            #pragma unroll
            for (int i2 = 0; i2 < 16; ++i2) {
                int ch = sq + 4 * i2;
                float4 hv = __ldcg((const float4*)(hb + ch * 4));
                *(float4*)(arow + I_ + ch * 4) = hv;
            }
            __syncthreads();
            gemm_range(32, 96, pA, pW, acc);   // h-part (k = 128..383)
        }

        // ---- epilogue: activations, register-resident c/h, packed-seq freeze ----
        float* hout = g_h[t & 1];
        #pragma unroll
        for (int i = 0; i < 4; ++i) {
            float xi = hsum(acc[i][0]);
            float xf = hsum(acc[i][1]);
            float xg = hsum(acc[i][2]);
            float xo = hsum(acc[i][3]);
            if (t < lsm[tr * 4 + i]) {
                float ig = sigm(xi), fg = sigm(xf);
                float gg = tanhf(xg), og = sigm(xo);
                c_reg[i] = fg * c_reg[i] + ig * gg;
                h_reg[i] = og * tanhf(c_reg[i]);
            }
            hout[(row0 + tr * 4 + i) * H_ + j0 + tc] = h_reg[i];   // frozen rows re-write old h
        }

        if (t < T_ - 1) {
            // arrive (release h(t)), then do h-independent work while others catch up
            __syncthreads();
            if (tid == 0) {
                unsigned old;
                asm volatile("atom.add.release.gpu.u32 %0, [%1], %2;"
                             : "=r"(old) : "l"(&g_bar_count), "r"(1u) : "memory");
                if (old == NBLK - 1) {
                    asm volatile("st.relaxed.gpu.u32 [%0], %1;"
                                 :: "l"(&g_bar_count), "r"(0u) : "memory");
                    asm volatile("red.add.release.gpu.u32 [%0], %1;"
                                 :: "l"(&g_bar_gen), "r"(1u) : "memory");
                }
            }
            // stage x(t+1) + x-part GEMM for next step (overlaps barrier skew)
            const float* xr = xbase + (size_t)(t + 1) * I_;
            #pragma unroll
            for (int i2 = 0; i2 < 8; ++i2) {
                int ch = sq + 4 * i2;
                *(float4*)(arow + ch * 4) = __ldg((const float4*)(xr + ch * 4));
            }
            __syncthreads();
            #pragma unroll
            for (int i = 0; i < 4; ++i)
                #pragma unroll
                for (int g = 0; g < 4; ++g) acc[i][g] = bias_d[g];
            gemm_range(0, 32, pA, pW, acc);
        }
    }
}

// ============================================================================
// LayerNorm over final hidden state (buffer (T-1)&1 = 1): one warp per row
// ============================================================================
__global__ void ln_kernel(const float* __restrict__ gamma,
                          const float* __restrict__ beta,
                          float* __restrict__ out)
{
    int w    = (int)((blockIdx.x * blockDim.x + threadIdx.x) >> 5);
    int lane = threadIdx.x & 31;
    if (w >= B_) return;
    const float* hr = g_h[1] + w * H_;
    float s = 0.0f, s2 = 0.0f;
    #pragma unroll
    for (int k = lane; k < H_; k += 32) { float v = hr[k]; s += v; s2 += v * v; }
    #pragma unroll
    for (int o = 16; o > 0; o >>= 1) {
        s  += __shfl_xor_sync(0xffffffffu, s,  o);
        s2 += __shfl_xor_sync(0xffffffffu, s2, o);
    }
    float mu  = s * (1.0f / H_);
    float var = fmaxf(s2 * (1.0f / H_) - mu * mu, 0.0f);
    float inv = rsqrtf(var + 1e-5f);
    #pragma unroll
    for (int k = lane; k < H_; k += 32) {
        out[w * H_ + k] = (hr[k] - mu) * inv * gamma[k] + beta[k];
    }
}

extern "C" void kernel_launch(void* const* d_in, const int* in_sizes, int n_in,
                              void* d_out, int out_size)
{
    const float* X     = (const float*)d_in[0];
    const int*   lens  = (const int*)  d_in[1];
    const float* W_ih  = (const float*)d_in[2];
    const float* W_hh  = (const float*)d_in[3];
    const float* b_ih  = (const float*)d_in[4];
    const float* b_hh  = (const float*)d_in[5];
    const float* gamma = (const float*)d_in[6];
    const float* beta  = (const float*)d_in[7];
    float*       out   = (float*)d_out;

    cudaFuncSetAttribute(lstm_persistent,
                         cudaFuncAttributeMaxDynamicSharedMemorySize, SMEM_BYTES);

    lstm_persistent<<<NBLK, NTHR, SMEM_BYTES>>>(X, lens, W_ih, W_hh, b_ih, b_hh);
    ln_kernel<<<(B_ * 32 + NTHR - 1) / NTHR, NTHR>>>(gamma, beta, out);
}